// round 2
// baseline (speedup 1.0000x reference)
#include <cuda_runtime.h>
#include <cstdint>

// STC_LIF recurrence, exact-fp32 sparse formulation.
//
// x [128, 4096, 128] == xs [512, 1024, 128] (reshape is identity), out same.
// State (m, s) is [1024, 128]; rows independent -> 1 warp per row, persistent
// loop over all 512 steps. s is exactly binary, so s @ W^T is a sparse sum of
// fp32 W rows, accumulated in ascending-k order with bias added last — this
// matches a dense fp32 fma matvec bit-for-bit (1.0*W products exact, +0.0
// no-ops). tanh uses the XLA/Eigen rational approximation to match jnp.tanh.

#define NSTEP 512
#define BATCH 1024
#define DIM 128
#define WARPS_PER_CTA 8
#define NCTAS (BATCH / WARPS_PER_CTA)       // 128
#define NTHREADS (WARPS_PER_CTA * 32)       // 256
#define SMEM_BYTES (DIM * DIM * 4)          // 64 KB: permuted W^T

// XLA / Eigen fast tanh for f32 (rational approx, clamp at 7.90531110763549805,
// identity below |x| < 0.0004). Matches jnp.tanh lowering.
__device__ __forceinline__ float xla_tanh(float x) {
    float cx = fmaxf(fminf(x, 7.90531110763549805f), -7.90531110763549805f);
    float x2 = __fmul_rn(cx, cx);
    float p = __fmaf_rn(x2, -2.76076847742355e-16f, 2.00018790482477e-13f);
    p = __fmaf_rn(x2, p, -8.60467152213735e-11f);
    p = __fmaf_rn(x2, p, 5.12229709037114e-08f);
    p = __fmaf_rn(x2, p, 1.48572235717979e-05f);
    p = __fmaf_rn(x2, p, 6.37261928875436e-04f);
    p = __fmaf_rn(x2, p, 4.89352455891786e-03f);
    p = __fmul_rn(cx, p);
    float q = __fmaf_rn(x2, 1.19825839466702e-06f, 1.18534705686654e-04f);
    q = __fmaf_rn(x2, q, 2.26843463243900e-03f);
    q = __fmaf_rn(x2, q, 4.89352518554385e-03f);
    float t = __fdiv_rn(p, q);
    return (fabsf(x) < 0.0004f) ? x : t;
}

__global__ void __launch_bounds__(NTHREADS, 1)
stc_lif_kernel(const float* __restrict__ x,
               const float* __restrict__ mem0,
               const float* __restrict__ sp0,
               const float* __restrict__ W,      // [D, D], z[d] = sum_k s[k]*W[d,k]
               const float* __restrict__ bias,   // [D]
               float* __restrict__ out)
{
    // WTp[k*32 + l] is a float4 whose component c holds W[(32c + l)*DIM + k].
    // For active k, lane l loads one float4 = W[d, k] for its 4 dims
    // d = 32c + l. Conflict-free LDS.128 (lanes hit 32 consecutive float4s).
    extern __shared__ float4 WTp[];

    const int tid  = threadIdx.x;
    const int lane = tid & 31;
    const int warp = tid >> 5;
    const int row  = blockIdx.x * WARPS_PER_CTA + warp;   // 0..1023

    // One-time permuted transpose of W into shared.
    for (int e = tid; e < DIM * 32; e += NTHREADS) {
        int k = e >> 5, l = e & 31;
        float4 v;
        v.x = W[(l      ) * DIM + k];
        v.y = W[(32 + l ) * DIM + k];
        v.z = W[(64 + l ) * DIM + k];
        v.w = W[(96 + l ) * DIM + k];
        WTp[e] = v;
    }
    __syncthreads();

    // This lane's 4 dims: d_c = 32c + lane.
    const float b0 = bias[lane], b1 = bias[32 + lane],
                b2 = bias[64 + lane], b3 = bias[96 + lane];

    const float* mrow = mem0 + (size_t)row * DIM;
    float m0 = mrow[lane], m1 = mrow[32 + lane],
          m2 = mrow[64 + lane], m3 = mrow[96 + lane];

    // Spike bitmask: word g holds k in [32g, 32g+32); bit l of word g is the
    // spike of dim 32g + l -> ballot over this lane's group-g spike value.
    const float* srow = sp0 + (size_t)row * DIM;
    unsigned msk0 = __ballot_sync(0xffffffffu, srow[lane]      != 0.0f);
    unsigned msk1 = __ballot_sync(0xffffffffu, srow[32 + lane] != 0.0f);
    unsigned msk2 = __ballot_sync(0xffffffffu, srow[64 + lane] != 0.0f);
    unsigned msk3 = __ballot_sync(0xffffffffu, srow[96 + lane] != 0.0f);

    const size_t step_stride = (size_t)BATCH * DIM;   // 131072
    const float* xp = x   + (size_t)row * DIM + lane;
    float*       op = out + (size_t)row * DIM + lane;

    // Prefetch x for step 0.
    float xa0 = xp[0], xa1 = xp[32], xa2 = xp[64], xa3 = xp[96];

    const float4* Wl = WTp + lane;

    for (int i = 0; i < NSTEP; i++) {
        // Prefetch next step's x (last iter re-reads step 0; value unused —
        // keeps the load unconditional and in-bounds).
        const float* xq = (i + 1 < NSTEP) ? (xp + step_stride) : (x + (size_t)row * DIM + lane);
        float xn0 = xq[0], xn1 = xq[32], xn2 = xq[64], xn3 = xq[96];

        // z[d] = sum over active k (ascending) of W[d, k]; bias added last.
        float z0 = 0.0f, z1 = 0.0f, z2 = 0.0f, z3 = 0.0f;
        #pragma unroll
        for (int g = 0; g < 4; g++) {
            unsigned bits = (g == 0) ? msk0 : (g == 1) ? msk1 : (g == 2) ? msk2 : msk3;
            const float4* base = Wl + g * 1024;   // k = 32g + t -> entry k*32 + lane
            while (bits) {
                int t = __ffs(bits) - 1;
                bits &= bits - 1;
                float4 wv = base[t * 32];
                z0 = __fadd_rn(z0, wv.x);
                z1 = __fadd_rn(z1, wv.y);
                z2 = __fadd_rn(z2, wv.z);
                z3 = __fadd_rn(z3, wv.w);
            }
        }

        // gamma = (1 + tanh(z + b)) * 0.5   (unfused, matching XLA rounding)
        float t0 = xla_tanh(__fadd_rn(z0, b0));
        float t1 = xla_tanh(__fadd_rn(z1, b1));
        float t2 = xla_tanh(__fadd_rn(z2, b2));
        float t3 = xla_tanh(__fadd_rn(z3, b3));
        float g0 = __fmul_rn(__fadd_rn(1.0f, t0), 0.5f);
        float g1 = __fmul_rn(__fadd_rn(1.0f, t1), 0.5f);
        float g2 = __fmul_rn(__fadd_rn(1.0f, t2), 0.5f);
        float g3 = __fmul_rn(__fadd_rn(1.0f, t3), 0.5f);

        // m = m + x * gamma  (mul then add, unfused)
        m0 = __fadd_rn(m0, __fmul_rn(xa0, g0));
        m1 = __fadd_rn(m1, __fmul_rn(xa1, g1));
        m2 = __fadd_rn(m2, __fmul_rn(xa2, g2));
        m3 = __fadd_rn(m3, __fmul_rn(xa3, g3));

        // spike = (m - 1 >= 0); m = m * (1 - spike)  (== reset to 0 on spike)
        bool f0 = (m0 >= 1.0f), f1 = (m1 >= 1.0f), f2 = (m2 >= 1.0f), f3 = (m3 >= 1.0f);
        float s0 = f0 ? 1.0f : 0.0f, s1 = f1 ? 1.0f : 0.0f;
        float s2 = f2 ? 1.0f : 0.0f, s3 = f3 ? 1.0f : 0.0f;
        m0 = f0 ? 0.0f : m0;  m1 = f1 ? 0.0f : m1;
        m2 = f2 ? 0.0f : m2;  m3 = f3 ? 0.0f : m3;

        op[0]  = s0;  op[32] = s1;  op[64] = s2;  op[96] = s3;

        msk0 = __ballot_sync(0xffffffffu, f0);
        msk1 = __ballot_sync(0xffffffffu, f1);
        msk2 = __ballot_sync(0xffffffffu, f2);
        msk3 = __ballot_sync(0xffffffffu, f3);

        xa0 = xn0; xa1 = xn1; xa2 = xn2; xa3 = xn3;
        xp += step_stride;
        op += step_stride;
    }
}

extern "C" void kernel_launch(void* const* d_in, const int* in_sizes, int n_in,
                              void* d_out, int out_size)
{
    (void)in_sizes; (void)n_in; (void)out_size;
    const float* x    = (const float*)d_in[0];
    const float* mem0 = (const float*)d_in[1];
    const float* sp0  = (const float*)d_in[2];
    const float* Wgs  = (const float*)d_in[3];
    const float* bgs  = (const float*)d_in[4];
    // d_in[5], d_in[6] (W_gt_w, W_gt_b) are dead in the reference's 3D branch.
    float* out = (float*)d_out;

    (void)cudaFuncSetAttribute(stc_lif_kernel,
                               cudaFuncAttributeMaxDynamicSharedMemorySize,
                               SMEM_BYTES);
    stc_lif_kernel<<<NCTAS, NTHREADS, SMEM_BYTES>>>(x, mem0, sp0, Wgs, bgs, out);
}